// round 8
// baseline (speedup 1.0000x reference)
#include <cuda_runtime.h>
#include <cuda_fp16.h>
#include <cstdint>

#define NV 40962
#define KR 19
#define NC 64            // C_in == C_out == 64
#define NBATCH 4
#define TILE_M 128
#define TILES_PER_B 321  // ceil(40962/128)
#define NTILES (NBATCH * TILES_PER_B)

#define ROW_STRIDE 144   // 9*16: bank-group(r) = 9r mod 8 = r -> conflict-free, no swizzle
#define W_ROW_HALFS 72   // 144 bytes

// -------- device scratch (allocation-free rule: __device__ globals) --------
// x[b][v][64] fp16, 128B per vertex row (contiguous -> one bulk op per gather)
__device__ __align__(1024) __half g_xt[(size_t)NBATCH * NV * NC];   // ~21 MB
// W padded to 144B rows: g_w[k][o][72], chunk k = 9216 contiguous bytes
__device__ __align__(1024) __half g_w[KR * NC * W_ROW_HALFS];       // ~175 KB

// ---------------------------- helpers ----------------------------------
__device__ __forceinline__ uint32_t smem_to_u32(const void* p) {
    uint32_t a;
    asm("{ .reg .u64 t; cvta.to.shared.u64 t, %1; cvt.u32.u64 %0, t; }"
        : "=r"(a) : "l"(p));
    return a;
}

__device__ __forceinline__ void bulk_g2s(uint32_t dst, const void* src,
                                         uint32_t bytes, uint32_t mbar) {
    asm volatile(
        "cp.async.bulk.shared::cluster.global.mbarrier::complete_tx::bytes "
        "[%0], [%1], %2, [%3];"
        :: "r"(dst), "l"(src), "r"(bytes), "r"(mbar) : "memory");
}

#define MBARRIER_INIT(mbar, count) \
    asm volatile("mbarrier.init.shared.b64 [%0], %1;" \
        :: "r"((uint32_t)(mbar)), "r"((uint32_t)(count)) : "memory")

#define MBARRIER_EXPECT_TX(mbar, bytes) \
    asm volatile("mbarrier.arrive.expect_tx.shared.b64 _, [%0], %1;" \
        :: "r"((uint32_t)(mbar)), "r"((uint32_t)(bytes)) : "memory")

#define MBARRIER_WAIT_PARITY(mbar_smem_addr, phase_parity) do { \
    uint32_t _mbar = (uint32_t)(mbar_smem_addr); \
    uint32_t _parity = (uint32_t)(phase_parity); \
    uint32_t _done; \
    asm volatile( \
        "{\n\t.reg .pred p;\n\t" \
        "mbarrier.try_wait.parity.acquire.cta.shared::cta.b64 p, [%1], %2;\n\t" \
        "selp.b32 %0, 1, 0, p;\n\t}" \
        : "=r"(_done) : "r"(_mbar), "r"(_parity) : "memory"); \
    if (!_done) { \
        asm volatile( \
            "{\n\t.reg .pred P1;\n\t" \
            "WAIT_LOOP_%=:\n\t" \
            "mbarrier.try_wait.parity.acquire.cta.shared::cta.b64 P1, [%0], %1, 0x989680;\n\t" \
            "@P1 bra.uni WAIT_DONE_%=;\n\t" \
            "bra.uni WAIT_LOOP_%=;\n\t" \
            "WAIT_DONE_%=:\n\t}" \
            :: "r"(_mbar), "r"(_parity) : "memory"); \
    } \
} while (0)

__device__ __forceinline__ void ldsm_x4(uint32_t& r0, uint32_t& r1, uint32_t& r2,
                                        uint32_t& r3, uint32_t a) {
    asm volatile("ldmatrix.sync.aligned.m8n8.x4.shared.b16 {%0,%1,%2,%3}, [%4];"
                 : "=r"(r0), "=r"(r1), "=r"(r2), "=r"(r3) : "r"(a));
}

__device__ __forceinline__ void mma_f16(float* c, uint32_t a0, uint32_t a1,
                                        uint32_t a2, uint32_t a3,
                                        uint32_t b0, uint32_t b1) {
    asm volatile(
        "mma.sync.aligned.m16n8k16.row.col.f32.f16.f16.f32 "
        "{%0,%1,%2,%3}, {%4,%5,%6,%7}, {%8,%9}, {%0,%1,%2,%3};"
        : "+f"(c[0]), "+f"(c[1]), "+f"(c[2]), "+f"(c[3])
        : "r"(a0), "r"(a1), "r"(a2), "r"(a3), "r"(b0), "r"(b1));
}

// ------------------------------ prep kernels --------------------------------
// W[o][19*64] -> g_w[k][o][0..63] fp16 at 144B row stride (pad bytes never read)
__global__ void prep_w_kernel(const float* __restrict__ W) {
    int i = blockIdx.x * blockDim.x + threadIdx.x;
    if (i >= NC * KR * NC) return;
    int o = i / (KR * NC);
    int kk = i % (KR * NC);
    int k = kk >> 6, c = kk & 63;
    g_w[((size_t)k * NC + o) * W_ROW_HALFS + c] = __float2half(W[i]);
}

// Transpose x[b][c][v] -> xt[b][v][c] fp16
__global__ void prep_x_kernel(const float* __restrict__ x) {
    __shared__ float s[64][65];
    int b = blockIdx.y;
    int v0 = blockIdx.x * 64;
    int tid = threadIdx.x;  // 256
    for (int i = tid; i < 64 * 64; i += 256) {
        int c = i >> 6, vi = i & 63;
        int v = v0 + vi;
        s[c][vi] = (v < NV) ? x[((size_t)b * NC + c) * NV + v] : 0.f;
    }
    __syncthreads();
    for (int i = tid; i < 64 * 32; i += 256) {
        int vi = i >> 5, g = i & 31;
        int v = v0 + vi;
        if (v >= NV) continue;
        int c0 = g * 2;
        __half2 h2 = __floats2half2_rn(s[c0][vi], s[c0 + 1][vi]);
        *(__half2*)(g_xt + ((size_t)b * NV + v) * NC + c0) = h2;
    }
}

// ------------------------------ main kernel ---------------------------------
// smem layout (bytes):
#define OFF_IDX   0          // 128*19*4 = 9728
#define OFF_BIAS  9728       // 64 floats
#define OFF_MBAR  9984       // 3 x 8B mbarriers
#define OFF_A     10240      // 3 stages x (128 rows x 144B) = 55296
#define OFF_W     65536      // 3 stages x (64 rows x 144B)  = 27648
#define SMEM_TOTAL 93184
#define A_STAGE 18432
#define W_STAGE 9216
#define CHUNK_TX (TILE_M * 128 + W_STAGE)   // 16384 + 9216 = 25600

__global__ __launch_bounds__(256, 2) void conv_main(const int* __restrict__ neigh,
                                                    const float* __restrict__ bias,
                                                    float* __restrict__ out) {
    extern __shared__ char smem[];
    uint32_t sb = smem_to_u32(smem);
    const int tid = threadIdx.x;
    const int wid = tid >> 5, lid = tid & 31;
    const int b = blockIdx.x / TILES_PER_B;
    const int t = blockIdx.x % TILES_PER_B;
    const int vbase = t * TILE_M;
    int rows = NV - vbase; if (rows > TILE_M) rows = TILE_M;

    if (tid < NC) ((float*)(smem + OFF_BIAS))[tid] = bias[tid];
    if (tid < 3)  MBARRIER_INIT(sb + OFF_MBAR + tid * 8, 1);

    // neighbor indices -> smem
    int* s_idx = (int*)(smem + OFF_IDX);
    {
        int tot = rows * KR;
        const int* src = neigh + (size_t)vbase * KR;
        for (int i = tid; i < tot; i += 256) s_idx[i] = src[i];
    }
    __syncthreads();

    const __half* xt = g_xt + (size_t)b * NV * NC;

    // ---- TMA-bulk gather of chunk k into stage k%3 ----
    // threads 0-127: one 128B vertex-row bulk each; thread 128: W chunk (one 9216B bulk);
    // thread 0: expect_tx (single arrival; tx accounting is commutative with completions).
    auto issue_chunk = [&](int k) {
        int stage = k % 3;
        uint32_t mbar = sb + OFF_MBAR + stage * 8;
        if (tid == 0) MBARRIER_EXPECT_TX(mbar, CHUNK_TX);
        if (tid < TILE_M) {
            int r = tid;
            int rr = (r < rows) ? r : 0;
            int v = s_idx[rr * KR + k];
            bulk_g2s(sb + OFF_A + stage * A_STAGE + r * ROW_STRIDE,
                     xt + (size_t)v * NC, 128, mbar);
        } else if (tid == TILE_M) {
            bulk_g2s(sb + OFF_W + stage * W_STAGE,
                     (const char*)g_w + (size_t)k * W_STAGE, W_STAGE, mbar);
        }
    };

    // ---- warp tiling: 4 M-warps x 2 N-warps; warp tile 32x32 ----
    const int wm = wid & 3;
    const int wn = wid >> 2;
    float acc[2][4][4];
    #pragma unroll
    for (int mt = 0; mt < 2; mt++)
        #pragma unroll
        for (int nt = 0; nt < 4; nt++)
            #pragma unroll
            for (int i = 0; i < 4; i++) acc[mt][nt][i] = 0.f;

    // ldmatrix lane address components (144B row stride, no swizzle)
    const uint32_t aRow = (uint32_t)(wm * 32 + (lid & 7) + 8 * ((lid >> 3) & 1)) * ROW_STRIDE;
    const uint32_t aColLane = (uint32_t)(lid >> 4) << 4;
    const uint32_t bRow = (uint32_t)(wn * 32 + (lid & 7) + 8 * (lid >> 4)) * ROW_STRIDE;
    const uint32_t bColLane = (uint32_t)((lid >> 3) & 1) << 4;
    const uint32_t MT_STEP = 16u * ROW_STRIDE;   // 16 rows

    // 3-stage ring, issue-ahead-2, one __syncthreads per chunk.
    // Stage-reuse safety: issue(k+2) targets stage (k+2)%3 == (k-1)%3 and happens
    // after the end-of-iter(k-1) barrier, i.e., after ALL warps finished MMA(k-1).
    // expect_tx re-arm safety: previous phase of that mbar (chunk k-1) was waited
    // on by all threads before that same barrier.
    issue_chunk(0);
    issue_chunk(1);

    for (int k = 0; k < KR; k++) {
        if (k + 2 < KR) issue_chunk(k + 2);

        MBARRIER_WAIT_PARITY(sb + OFF_MBAR + (k % 3) * 8, (k / 3) & 1);

        const int stage = k % 3;
        const uint32_t aT = sb + OFF_A + stage * A_STAGE;
        const uint32_t bT = sb + OFF_W + stage * W_STAGE;

        #pragma unroll
        for (int ks = 0; ks < 4; ks++) {
            const uint32_t kb = (uint32_t)(ks * 32);
            uint32_t Af[2][4];
            #pragma unroll
            for (int mt = 0; mt < 2; mt++) {
                uint32_t off = aRow + (uint32_t)mt * MT_STEP + kb + aColLane;
                ldsm_x4(Af[mt][0], Af[mt][1], Af[mt][2], Af[mt][3], aT + off);
            }
            uint32_t Bf[8];
            #pragma unroll
            for (int p = 0; p < 2; p++) {
                uint32_t off = bRow + (uint32_t)p * MT_STEP + kb + bColLane;
                ldsm_x4(Bf[p * 4 + 0], Bf[p * 4 + 1], Bf[p * 4 + 2], Bf[p * 4 + 3],
                        bT + off);
            }
            #pragma unroll
            for (int mt = 0; mt < 2; mt++)
                #pragma unroll
                for (int nt = 0; nt < 4; nt++)
                    mma_f16(acc[mt][nt], Af[mt][0], Af[mt][1], Af[mt][2], Af[mt][3],
                            Bf[nt * 2], Bf[nt * 2 + 1]);
        }
        __syncthreads();
    }

    // ---- epilogue: stage via smem for coalesced [o][v] stores ----
    float* s_out = (float*)(smem + OFF_A);   // 32 KB within A stages 0-1
    #pragma unroll
    for (int mt = 0; mt < 2; mt++) {
        int r = wm * 32 + mt * 16 + (lid >> 2);
        #pragma unroll
        for (int nt = 0; nt < 4; nt++) {
            int o = wn * 32 + nt * 8 + (lid & 3) * 2;
            s_out[(o + 0) * 128 + r]     = acc[mt][nt][0];
            s_out[(o + 1) * 128 + r]     = acc[mt][nt][1];
            s_out[(o + 0) * 128 + r + 8] = acc[mt][nt][2];
            s_out[(o + 1) * 128 + r + 8] = acc[mt][nt][3];
        }
    }
    __syncthreads();

    const float* bs = (const float*)(smem + OFF_BIAS);
    float* ob = out + (size_t)b * NC * NV + vbase;
    #pragma unroll
    for (int i = 0; i < 32; i++) {
        int idx = tid + i * 256;
        int o = idx >> 7, v = idx & 127;
        if (v < rows) ob[(size_t)o * NV + v] = s_out[idx] + bs[o];
    }
}

// ------------------------------ launch --------------------------------------
extern "C" void kernel_launch(void* const* d_in, const int* in_sizes, int n_in,
                              void* d_out, int out_size) {
    const float* x     = (const float*)d_in[0];
    const int*   neigh = (const int*)d_in[1];
    const float* W     = (const float*)d_in[2];
    const float* bias  = (const float*)d_in[3];
    float* out = (float*)d_out;

    cudaFuncSetAttribute(conv_main, cudaFuncAttributeMaxDynamicSharedMemorySize, SMEM_TOTAL);

    prep_w_kernel<<<(NC * KR * NC + 255) / 256, 256>>>(W);
    prep_x_kernel<<<dim3((NV + 63) / 64, NBATCH), 256>>>(x);
    conv_main<<<NTILES, 256, SMEM_TOTAL>>>(neigh, bias, out);
}